// round 2
// baseline (speedup 1.0000x reference)
#include <cuda_runtime.h>
#include <cuda_bf16.h>
#include <cstdint>
#include <cstddef>

// Problem dims
#define BB 8
#define TT 256
#define UU 64
#define HH 640
#define VV 1025
#define NROWS (BB*TT*UU)   // 131072
#define NPAD 1024          // GEMM covers cols 0..1023; col 1024 via GEMV in k_tanhA

// Feature gate: tcgen05 only exists on the "a" target. On the baseline
// sm_103 pass this is 0 and the portable mma.sync path compiles instead.
#if defined(__CUDA_ARCH__) && (defined(__CUDA_ARCH_FEAT_SM103_ALL) || defined(__CUDA_ARCH_FEAT_SM100_ALL))
#define USE_TCGEN05 1
#else
#define USE_TCGEN05 0
#endif

// Scratch (device globals: allocation-free rule)
__device__ __nv_bfloat16 g_A[(size_t)NROWS * HH];     // tanh(enc+dec) bf16, 168MB
__device__ __nv_bfloat16 g_Wb[(size_t)NPAD * HH];     // W rows 0..1023 bf16

// ---------------------------------------------------------------------------
// Helpers
// ---------------------------------------------------------------------------
__device__ __forceinline__ uint32_t smem_u32(const void* p) {
    return (uint32_t)__cvta_generic_to_shared(p);
}
__device__ __forceinline__ void cp16(uint32_t s, const void* g) {
    asm volatile("cp.async.cg.shared.global [%0], [%1], 16;\n" :: "r"(s), "l"(g));
}
__device__ __forceinline__ void cp_commit() { asm volatile("cp.async.commit_group;\n" ::: "memory"); }
__device__ __forceinline__ void cp_wait0() { asm volatile("cp.async.wait_group 0;\n" ::: "memory"); }
__device__ __forceinline__ void cp_wait1() { asm volatile("cp.async.wait_group 1;\n" ::: "memory"); }

// ---------------------------------------------------------------------------
// K0: W fp32 -> bf16 (rows 0..1023)
// ---------------------------------------------------------------------------
__global__ void k_convW(const float* __restrict__ W) {
    int i = (blockIdx.x * blockDim.x + threadIdx.x) * 2;
    if (i < NPAD * HH) {
        float2 w = *(const float2*)(W + i);
        *(__nv_bfloat162*)(g_Wb + i) = __floats2bfloat162_rn(w.x, w.y);
    }
}

// ---------------------------------------------------------------------------
// K1: A = tanh(enc+dec) -> bf16 scratch, fused GEMV for blank column 1024
// One warp per row; 8 rows per 256-thread block.
// ---------------------------------------------------------------------------
__global__ void __launch_bounds__(256) k_tanhA(
    const float* __restrict__ enc, const float* __restrict__ dec,
    const float* __restrict__ W, const float* __restrict__ bias,
    float* __restrict__ out)
{
    int warp = threadIdx.x >> 5, lane = threadIdx.x & 31;
    int row  = blockIdx.x * 8 + warp;
    int b = row >> 14;
    int t = (row >> 6) & 255;
    int u = row & 63;
    const float* e  = enc + (size_t)(b * TT + t) * HH;
    const float* d  = dec + (size_t)(b * UU + u) * HH;
    const float* wl = W + (size_t)NPAD * HH;   // W[1024,:]
    __nv_bfloat16* arow = g_A + (size_t)row * HH;

    float acc = 0.f;
#pragma unroll
    for (int j = 0; j < 10; j++) {
        int k = j * 64 + lane * 2;
        float2 ev = *(const float2*)(e + k);
        float2 dv = *(const float2*)(d + k);
        float x0 = ev.x + dv.x, x1 = ev.y + dv.y;
        float h0, h1;
        asm("tanh.approx.f32 %0, %1;" : "=f"(h0) : "f"(x0));
        asm("tanh.approx.f32 %0, %1;" : "=f"(h1) : "f"(x1));
        *(__nv_bfloat162*)(arow + k) = __floats2bfloat162_rn(h0, h1);
        float2 wv = *(const float2*)(wl + k);
        acc = fmaf(h0, wv.x, acc);
        acc = fmaf(h1, wv.y, acc);
    }
#pragma unroll
    for (int o = 16; o; o >>= 1) acc += __shfl_xor_sync(0xffffffffu, acc, o);
    if (lane == 0) out[(size_t)row * VV + 1024] = acc + bias[1024];
}

// ---------------------------------------------------------------------------
// K2: GEMM. CTA covers rows [m0,m0+128), cols [n0,n0+512) of the logits.
// Portable path: mma.sync m16n8k16 bf16, 4 sub-tiles of 128x128, BK=64,
// 2-stage cp.async double buffer. (tcgen05 path retained behind USE_TCGEN05.)
// ---------------------------------------------------------------------------
#define SMEM_TOTAL 167936

#if !USE_TCGEN05
// ---- mma.sync path -------------------------------------------------------
#define PADE 72                 // bf16 elems per smem row (64 data + 8 pad)
#define STG_BYTES (128*PADE*2)  // 18432 per tile stage
#define MA_A0 0
#define MA_A1 STG_BYTES
#define MA_B0 (2*STG_BYTES)
#define MA_B1 (3*STG_BYTES)

__device__ __forceinline__ void mma16816(float* c, const uint32_t* a, const uint32_t* b) {
    asm volatile(
        "mma.sync.aligned.m16n8k16.row.col.f32.bf16.bf16.f32 "
        "{%0,%1,%2,%3}, {%4,%5,%6,%7}, {%8,%9}, {%0,%1,%2,%3};\n"
        : "+f"(c[0]), "+f"(c[1]), "+f"(c[2]), "+f"(c[3])
        : "r"(a[0]), "r"(a[1]), "r"(a[2]), "r"(a[3]), "r"(b[0]), "r"(b[1]));
}

__global__ void __launch_bounds__(256) k_gemm(const float* __restrict__ bias,
                                              float* __restrict__ out)
{
    extern __shared__ char smem[];
    uint32_t sbase = smem_u32(smem);
    int tid = threadIdx.x;
    int wid = tid >> 5, lane = tid & 31;
    int gid = lane >> 2, tig = lane & 3;
    int m0 = blockIdx.y * 128;
    int n0 = blockIdx.x * 512;

    int m_base = (wid & 3) * 32;   // 4 warps along M (32 rows each)
    int n_base = (wid >> 2) * 64;  // 2 warps along N (64 cols each)

    const uint32_t aoff[2] = {MA_A0, MA_A1};
    const uint32_t boff[2] = {MA_B0, MA_B1};

    for (int sub = 0; sub < 4; sub++) {
        const __nv_bfloat16* Abase = g_A  + (size_t)m0 * HH;
        const __nv_bfloat16* Bbase = g_Wb + (size_t)(n0 + sub * 128) * HH;

        auto load_stage = [&](int it, int s) {
            uint32_t ab = sbase + aoff[s];
            uint32_t bb = sbase + boff[s];
            const __nv_bfloat16* Ag = Abase + it * 64;
            const __nv_bfloat16* Bg = Bbase + it * 64;
#pragma unroll
            for (int j = 0; j < 4; j++) {      // 128 rows x 8 chunks of 16B
                int c = tid + j * 256;
                int r = c >> 3, cc = c & 7;
                cp16(ab + r * (PADE*2) + cc * 16, Ag + (size_t)r * HH + cc * 8);
            }
#pragma unroll
            for (int j = 0; j < 4; j++) {
                int c = tid + j * 256;
                int r = c >> 3, cc = c & 7;
                cp16(bb + r * (PADE*2) + cc * 16, Bg + (size_t)r * HH + cc * 8);
            }
            cp_commit();
        };

        float acc[2][8][4];
#pragma unroll
        for (int mt = 0; mt < 2; mt++)
#pragma unroll
            for (int nt = 0; nt < 8; nt++)
#pragma unroll
                for (int q = 0; q < 4; q++) acc[mt][nt][q] = 0.f;

        load_stage(0, 0);
        load_stage(1, 1);

        for (int kc = 0; kc < 10; kc++) {
            int s = kc & 1;
            if (kc == 9) cp_wait0(); else cp_wait1();
            __syncthreads();

            const uint32_t* As = (const uint32_t*)(smem + aoff[s]);
            const uint32_t* Bs = (const uint32_t*)(smem + boff[s]);
#pragma unroll
            for (int ks = 0; ks < 4; ks++) {
                int kh = ks * 8;   // k offset in units of 2 bf16 (b32 words)
                uint32_t a[2][4], b[8][2];
#pragma unroll
                for (int mt = 0; mt < 2; mt++) {
                    int r = m_base + mt * 16 + gid;
                    a[mt][0] = As[r * 36 + kh + tig];
                    a[mt][1] = As[(r + 8) * 36 + kh + tig];
                    a[mt][2] = As[r * 36 + kh + tig + 4];
                    a[mt][3] = As[(r + 8) * 36 + kh + tig + 4];
                }
#pragma unroll
                for (int nt = 0; nt < 8; nt++) {
                    int n = n_base + nt * 8 + gid;
                    b[nt][0] = Bs[n * 36 + kh + tig];
                    b[nt][1] = Bs[n * 36 + kh + tig + 4];
                }
#pragma unroll
                for (int mt = 0; mt < 2; mt++)
#pragma unroll
                    for (int nt = 0; nt < 8; nt++)
                        mma16816(acc[mt][nt], a[mt], b[nt]);
            }
            __syncthreads();                 // all warps done reading stage s
            if (kc + 2 < 10) load_stage(kc + 2, s);
        }

        // Epilogue: bias add, scalar fp32 stores (rows of 1025 are 4B-aligned only)
#pragma unroll
        for (int mt = 0; mt < 2; mt++) {
#pragma unroll
            for (int nt = 0; nt < 8; nt++) {
                int row = m0 + m_base + mt * 16 + gid;
                int col = n0 + sub * 128 + n_base + nt * 8 + tig * 2;
                float2 bi = *(const float2*)(bias + col);
                float* p0 = out + (size_t)row * VV + col;
                p0[0] = acc[mt][nt][0] + bi.x;
                p0[1] = acc[mt][nt][1] + bi.y;
                float* p1 = out + (size_t)(row + 8) * VV + col;
                p1[0] = acc[mt][nt][2] + bi.x;
                p1[1] = acc[mt][nt][3] + bi.y;
            }
        }
        __syncthreads();   // before next sub overwrites smem stages
    }
}

#else
// ---- tcgen05 path (active only under a true sm_103a/compute_103a pass) ----
#define SM_TMEMPTR 0
#define SM_MBAR    16
#define SM_BIAS    64
#define SM_A0      4096
#define SM_A1      (4096 + 16384)
#define SM_B0      36864
#define SM_B1      (36864 + 65536)
#define BK 64
#define KITERS (HH/BK)

__device__ __forceinline__ uint32_t sw128(uint32_t o) { return o ^ ((o >> 3) & 0x70); }
__device__ __forceinline__ uint64_t mk_desc(uint32_t addr) {
    return ((uint64_t)2 << 61) | ((uint64_t)1 << 46) | ((uint64_t)64 << 32) |
           ((uint64_t)1 << 16) | ((uint64_t)((addr >> 4) & 0x3FFF));
}
__device__ __forceinline__ void mbar_init(uint32_t a, uint32_t cnt) {
    asm volatile("mbarrier.init.shared.b64 [%0], %1;" :: "r"(a), "r"(cnt) : "memory");
}
__device__ __forceinline__ void mbar_wait(uint32_t a, uint32_t parity) {
    asm volatile(
        "{\n\t.reg .pred P;\n\t"
        "WLOOP%=:\n\t"
        "mbarrier.try_wait.parity.acquire.cta.shared::cta.b64 P, [%0], %1, 0x989680;\n\t"
        "@!P bra WLOOP%=;\n\t}"
        :: "r"(a), "r"(parity) : "memory");
}
#define IDESC ((1u<<4)|(1u<<7)|(1u<<10)|((256u/8u)<<17)|((128u/16u)<<24))
__device__ __forceinline__ void mma_f16_ss(uint32_t d, uint64_t a, uint64_t b,
                                           uint32_t idesc, bool acc) {
    uint32_t en = acc ? 1u : 0u;
    asm volatile(
        "{\n\t.reg .pred p;\n\t"
        "setp.ne.u32 p, %5, 0;\n\t"
        "tcgen05.mma.cta_group::1.kind::f16 [%0], %1, %2, %3, {%4, %4, %4, %4}, p;\n\t}"
        :: "r"(d), "l"(a), "l"(b), "r"(idesc), "r"(0u), "r"(en) : "memory");
}
__device__ __forceinline__ void tmem_ld32(uint32_t* r, uint32_t addr) {
    asm volatile(
        "tcgen05.ld.sync.aligned.32x32b.x32.b32 "
        "{%0, %1, %2, %3, %4, %5, %6, %7, "
        " %8, %9, %10, %11, %12, %13, %14, %15, "
        " %16, %17, %18, %19, %20, %21, %22, %23, "
        " %24, %25, %26, %27, %28, %29, %30, %31}, [%32];"
        : "=r"(r[0]),  "=r"(r[1]),  "=r"(r[2]),  "=r"(r[3]),
          "=r"(r[4]),  "=r"(r[5]),  "=r"(r[6]),  "=r"(r[7]),
          "=r"(r[8]),  "=r"(r[9]),  "=r"(r[10]), "=r"(r[11]),
          "=r"(r[12]), "=r"(r[13]), "=r"(r[14]), "=r"(r[15]),
          "=r"(r[16]), "=r"(r[17]), "=r"(r[18]), "=r"(r[19]),
          "=r"(r[20]), "=r"(r[21]), "=r"(r[22]), "=r"(r[23]),
          "=r"(r[24]), "=r"(r[25]), "=r"(r[26]), "=r"(r[27]),
          "=r"(r[28]), "=r"(r[29]), "=r"(r[30]), "=r"(r[31])
        : "r"(addr));
}

__global__ void __launch_bounds__(256) k_gemm(const float* __restrict__ bias,
                                              float* __restrict__ out)
{
    extern __shared__ char smem[];
    uint32_t sbase = smem_u32(smem);
    int tid = threadIdx.x;
    int wid = tid >> 5, lane = tid & 31;
    int m0 = blockIdx.y * 128;
    int n0 = blockIdx.x * 512;

    for (int i = tid; i < 512; i += 256)
        ((float*)(smem + SM_BIAS))[i] = bias[n0 + i];

    if (tid == 0) {
        mbar_init(sbase + SM_MBAR + 0, 1);
        mbar_init(sbase + SM_MBAR + 8, 1);
    }
    if (wid == 0) {
        asm volatile("tcgen05.alloc.cta_group::1.sync.aligned.shared::cta.b32 [%0], %1;"
                     :: "r"(sbase + SM_TMEMPTR), "r"(512) : "memory");
        asm volatile("tcgen05.relinquish_alloc_permit.cta_group::1.sync.aligned;" ::: "memory");
    }
    __syncthreads();
    uint32_t tmem;
    asm volatile("ld.shared.b32 %0, [%1];" : "=r"(tmem) : "r"(sbase + SM_TMEMPTR));

    const uint32_t aoff[2] = {SM_A0, SM_A1};
    const uint32_t boff[2] = {SM_B0, SM_B1};

    auto load_stage = [&](int it, int s) {
        const __nv_bfloat16* Ab = g_A  + (size_t)m0 * HH + it * BK;
        const __nv_bfloat16* Bb = g_Wb + (size_t)n0 * HH + it * BK;
        uint32_t abase = sbase + aoff[s];
        uint32_t bbase = sbase + boff[s];
#pragma unroll
        for (int j = 0; j < 4; j++) {
            int c = tid + j * 256;
            int r = c >> 3, cc = c & 7;
            cp16(abase + sw128(r * 128 + cc * 16), Ab + (size_t)r * HH + cc * 8);
        }
#pragma unroll
        for (int j = 0; j < 16; j++) {
            int c = tid + j * 256;
            int r = c >> 3, cc = c & 7;
            cp16(bbase + sw128(r * 128 + cc * 16), Bb + (size_t)r * HH + cc * 8);
        }
        cp_commit();
    };

    load_stage(0, 0);
    load_stage(1, 1);
    uint32_t ph[2] = {0, 0};

    for (int it = 0; it < KITERS; it++) {
        int s = it & 1;
        if (it == KITERS - 1) cp_wait0(); else cp_wait1();
        __syncthreads();

        if (wid == 0) {
            asm volatile("fence.proxy.async.shared::cta;" ::: "memory");
            if (lane == 0) {
                uint64_t ad  = mk_desc(sbase + aoff[s]);
                uint64_t bd0 = mk_desc(sbase + boff[s]);
                uint64_t bd1 = mk_desc(sbase + boff[s] + 256 * 128);
#pragma unroll
                for (int ks = 0; ks < 4; ks++) {
                    bool acc = (it > 0) || (ks > 0);
                    mma_f16_ss(tmem,       ad + ks * 2, bd0 + ks * 2, IDESC, acc);
                    mma_f16_ss(tmem + 256, ad + ks * 2, bd1 + ks * 2, IDESC, acc);
                }
                asm volatile(
                    "tcgen05.commit.cta_group::1.mbarrier::arrive::one.shared::cluster.b64 [%0];"
                    :: "r"(sbase + SM_MBAR + 8 * s) : "memory");
            }
        }
        if (it + 2 < KITERS) {
            mbar_wait(sbase + SM_MBAR + 8 * s, ph[s]);
            ph[s] ^= 1;
            load_stage(it + 2, s);
        }
    }

    mbar_wait(sbase + SM_MBAR + 8, ph[1]);
    asm volatile("tcgen05.fence::after_thread_sync;" ::: "memory");

    if (wid < 4) {
        uint32_t woff = (uint32_t)wid << 21;
        int row = m0 + wid * 32 + lane;
        float* orow = out + (size_t)row * VV + n0;
        const float* bs = (const float*)(smem + SM_BIAS);
        for (int cb = 0; cb < 16; cb++) {
            uint32_t r[32];
            tmem_ld32(r, tmem + woff + cb * 32);
            asm volatile("tcgen05.wait::ld.sync.aligned;" ::: "memory");
#pragma unroll
            for (int c = 0; c < 32; c++)
                orow[cb * 32 + c] = __uint_as_float(r[c]) + bs[cb * 32 + c];
        }
    }
    __syncthreads();
    if (wid == 0) {
        asm volatile("tcgen05.dealloc.cta_group::1.sync.aligned.b32 %0, %1;"
                     :: "r"(tmem), "r"(512));
    }
}
#endif  // USE_TCGEN05

// ---------------------------------------------------------------------------
// K3: in-place log_softmax over last dim (V=1025). One 256-thread block/row.
// ---------------------------------------------------------------------------
__global__ void __launch_bounds__(256) k_lsm(float* __restrict__ out) {
    int row = blockIdx.x;
    float* p = out + (size_t)row * VV;
    int tid = threadIdx.x;
    int wid = tid >> 5, lane = tid & 31;

    float v0 = p[tid], v1 = p[tid + 256], v2 = p[tid + 512], v3 = p[tid + 768];
    bool has5 = (tid == 0);
    float v4 = has5 ? p[1024] : -1e30f;

    float mx = fmaxf(fmaxf(v0, v1), fmaxf(v2, v3));
    mx = fmaxf(mx, v4);
#pragma unroll
    for (int o = 16; o; o >>= 1) mx = fmaxf(mx, __shfl_xor_sync(0xffffffffu, mx, o));

    __shared__ float red[8];
    if (lane == 0) red[wid] = mx;
    __syncthreads();
    if (tid < 8) {
        float m = red[tid];
#pragma unroll
        for (int o = 4; o; o >>= 1) m = fmaxf(m, __shfl_xor_sync(0xffu, m, o));
        if (tid == 0) red[0] = m;
    }
    __syncthreads();
    mx = red[0];
    __syncthreads();

    float s = __expf(v0 - mx) + __expf(v1 - mx) + __expf(v2 - mx) + __expf(v3 - mx);
    if (has5) s += __expf(v4 - mx);
#pragma unroll
    for (int o = 16; o; o >>= 1) s += __shfl_xor_sync(0xffffffffu, s, o);
    if (lane == 0) red[wid] = s;
    __syncthreads();
    if (tid < 8) {
        float t = red[tid];
#pragma unroll
        for (int o = 4; o; o >>= 1) t += __shfl_xor_sync(0xffu, t, o);
        if (tid == 0) red[0] = t;
    }
    __syncthreads();
    float lse = mx + logf(red[0]);

    p[tid]       = v0 - lse;
    p[tid + 256] = v1 - lse;
    p[tid + 512] = v2 - lse;
    p[tid + 768] = v3 - lse;
    if (has5) p[1024] = v4 - lse;
}

// ---------------------------------------------------------------------------
extern "C" void kernel_launch(void* const* d_in, const int* in_sizes, int n_in,
                              void* d_out, int out_size) {
    (void)in_sizes; (void)n_in; (void)out_size;
    const float* enc  = (const float*)d_in[0];
    const float* dec  = (const float*)d_in[1];
    const float* W    = (const float*)d_in[2];
    const float* bias = (const float*)d_in[3];
    float* out = (float*)d_out;

    k_convW<<<(NPAD * HH / 2 + 255) / 256, 256>>>(W);
    k_tanhA<<<NROWS / 8, 256>>>(enc, dec, W, bias, out);

    cudaFuncSetAttribute(k_gemm, cudaFuncAttributeMaxDynamicSharedMemorySize, SMEM_TOTAL);
    dim3 grid(NPAD / 512, NROWS / 128);   // (2, 1024)
    k_gemm<<<grid, 256, SMEM_TOTAL>>>(bias, out);

    k_lsm<<<NROWS, 256>>>(out);
}